// round 14
// baseline (speedup 1.0000x reference)
#include <cuda_runtime.h>
#include <cuda_fp16.h>
#include <cstdint>
#include <cstddef>

#define BROWS 4096
#define DIN   1024
#define DOUT  1024
#define LEAF  32
#define NTOT  (DOUT * LEAF)   // 32768

// ---------------- scratch (device globals: allocation-free) ----------------
__device__ __align__(128) __half d_xb[(size_t)BROWS * DIN];     // 8 MB   x fp16
__device__ __align__(128) __half d_pwb[(size_t)NTOT * DIN];     // 64 MB  pw packed [n=o*32+l][k=i]
__device__ __align__(128) float  d_gate[(size_t)BROWS * LEAF];  // 512 KB gates

// ---------------- helpers ----------------
static __device__ __forceinline__ uint32_t smem_u32(const void* p) {
    uint32_t a;
    asm("{ .reg .u64 t; cvta.to.shared.u64 t, %1; cvt.u32.u64 %0, t; }" : "=r"(a) : "l"(p));
    return a;
}
static __device__ __forceinline__ uint32_t swz(uint32_t o) {     // Swizzle<3,4,3>, 128B rows
    return o ^ ((o >> 3) & 0x70);
}
static __device__ __forceinline__ void cp_async16(uint32_t s, const void* g) {
    asm volatile("cp.async.cg.shared.global [%0], [%1], 16;" :: "r"(s), "l"(g));
}
static __device__ __forceinline__ void ldsm4(uint32_t* r, uint32_t addr) {
    asm volatile("ldmatrix.sync.aligned.m8n8.x4.shared.b16 {%0,%1,%2,%3}, [%4];"
                 : "=r"(r[0]), "=r"(r[1]), "=r"(r[2]), "=r"(r[3]) : "r"(addr));
}
static __device__ __forceinline__ void mma16816(float* d, const uint32_t* a,
                                                uint32_t b0, uint32_t b1) {
    asm volatile("mma.sync.aligned.m16n8k16.row.col.f32.f16.f16.f32 "
                 "{%0,%1,%2,%3}, {%4,%5,%6,%7}, {%8,%9}, {%0,%1,%2,%3};"
                 : "+f"(d[0]), "+f"(d[1]), "+f"(d[2]), "+f"(d[3])
                 : "r"(a[0]), "r"(a[1]), "r"(a[2]), "r"(a[3]), "r"(b0), "r"(b1));
}

// ---------------- kernel 1: gating softmax + x fp32->fp16 ----------------
// Block (256 thr, 8 warps) handles 8 rows. Warp w computes the partial dot over
// DIN-slice [w*128, (w+1)*128) for ALL 8 rows (lane = leaf; gw loads amortized
// 8x), partials reduced through smem. 512 blocks -> 4096 warps (latency hidden).
__global__ void gating_kernel(const float* __restrict__ x, const float* __restrict__ gw,
                              const float* __restrict__ gb) {
    __shared__ float part[8][8][32];            // [warp][row][lane] = 8 KB
    const int tid  = threadIdx.x;
    const int lane = tid & 31;
    const int w    = tid >> 5;                  // 0..7
    const int r0   = blockIdx.x * 8;

    const float4* x4 = reinterpret_cast<const float4*>(x);

    float acc[8];
    #pragma unroll
    for (int r = 0; r < 8; ++r) acc[r] = 0.f;

    // dot pass over this warp's DIN slice: j in [w*32, w*32+32) float4-steps
    #pragma unroll 2
    for (int jj = 0; jj < 32; ++jj) {
        const int j = w * 32 + jj;
        const float* gp = gw + (j * 4) * LEAF + lane;
        const float g0 = gp[0 * LEAF];
        const float g1 = gp[1 * LEAF];
        const float g2 = gp[2 * LEAF];
        const float g3 = gp[3 * LEAF];
        #pragma unroll
        for (int r = 0; r < 8; ++r) {
            const float4 xv = x4[(size_t)(r0 + r) * (DIN / 4) + j];  // broadcast
            acc[r] = fmaf(xv.x, g0, acc[r]);
            acc[r] = fmaf(xv.y, g1, acc[r]);
            acc[r] = fmaf(xv.z, g2, acc[r]);
            acc[r] = fmaf(xv.w, g3, acc[r]);
        }
    }
    #pragma unroll
    for (int r = 0; r < 8; ++r) part[w][r][lane] = acc[r];

    // fp16 conversion of the block's 8 rows (independent of part[]; overlaps sync)
    #pragma unroll
    for (int u = 0; u < 8; ++u) {
        const int idx = u * 256 + tid;          // 2048 float4s = 8 rows x 256
        const int r   = idx >> 8;
        const int c   = idx & 255;
        const float4 xv = x4[(size_t)(r0 + r) * (DIN / 4) + c];
        __half2* hp = reinterpret_cast<__half2*>(d_xb + (size_t)(r0 + r) * DIN) + c * 2;
        hp[0] = __floats2half2_rn(xv.x, xv.y);
        hp[1] = __floats2half2_rn(xv.z, xv.w);
    }
    __syncthreads();

    // warp w finalizes row w: sum 8 partials, softmax over 32 leaves
    float a = gb[lane];
    #pragma unroll
    for (int k = 0; k < 8; ++k) a += part[k][w][lane];
    float m = a;
    #pragma unroll
    for (int o = 16; o; o >>= 1) m = fmaxf(m, __shfl_xor_sync(0xffffffff, m, o));
    const float e = expf(a - m);
    float s = e;
    #pragma unroll
    for (int o = 16; o; o >>= 1) s += __shfl_xor_sync(0xffffffff, s, o);
    d_gate[(size_t)(r0 + w) * LEAF + lane] = e / s;
}

// ---------------- kernel 2: pack pw [O,I,L] fp32 -> pwb [(o*32+l), i] fp16 ----------------
__global__ void pack_pw_kernel(const float* __restrict__ pw) {
    __shared__ float tile[64][33];                        // 64 i  x 32 l  (padded)
    const int o   = blockIdx.x;                           // 0..1023
    const int i0  = blockIdx.y * 64;                      // 0..960
    const int tid = threadIdx.x;                          // 256 threads
    const float* src = pw + ((size_t)o * DIN + i0) * LEAF;
    #pragma unroll
    for (int u = 0; u < 8; ++u) {                         // 2048 coalesced fp32 reads
        int idx = u * 256 + tid;
        tile[idx >> 5][idx & 31] = src[idx];
    }
    __syncthreads();
    __half2* dst2 = reinterpret_cast<__half2*>(d_pwb + ((size_t)o * LEAF) * DIN + i0);
    #pragma unroll
    for (int u = 0; u < 4; ++u) {                         // 1024 coalesced half2 writes
        int idx = u * 256 + tid;
        int l = idx >> 5, p = idx & 31;
        dst2[(size_t)l * (DIN / 2) + p] =
            __floats2half2_rn(tile[2 * p][l], tile[2 * p + 1][l]);
    }
}

// ---------------- kernel 3: mma.sync GEMM, 2 CTA/SM, 64x64 warp tile,
//                  register-level fragment double buffering ----------------
#define MT  128
#define NT  128
#define KT  64                       // halves per k-tile (128 B rows)
#define KI  (DIN / KT)               // 16
#define STG 3
#define SA_BYTES    (MT * KT * 2)    // 16384
#define SB_BYTES    (NT * KT * 2)    // 16384
#define STAGE_BYTES (SA_BYTES + SB_BYTES)          // 32768
#define SMEM_TOTAL  (STG * STAGE_BYTES)            // 98304 -> 2 CTAs/SM

static __device__ __forceinline__ void load_tile(uint32_t sb, int tid,
                                                 int m_base, int n_base, int ki, int buf) {
    const uint32_t abase = sb + buf * STAGE_BYTES;
    const uint32_t bbase = abase + SA_BYTES;
    const __half* ga  = d_xb  + (size_t)m_base * DIN + ki * KT;
    const __half* gbp = d_pwb + (size_t)n_base * DIN + ki * KT;
    #pragma unroll
    for (int u = 0; u < 16; ++u) {                        // 2048 x 16B chunks / 128 thr
        const int idx = u * 128 + tid;
        if (idx < 1024) {                                 // A: 128 rows x 8 chunks
            const int r = idx >> 3, c = idx & 7;
            cp_async16(abase + swz((uint32_t)(r * 128 + c * 16)),
                       ga + (size_t)r * DIN + c * 8);
        } else {                                          // B: 128 rows x 8 chunks
            const int j = idx - 1024;
            const int r = j >> 3, c = j & 7;
            cp_async16(bbase + swz((uint32_t)(r * 128 + c * 16)),
                       gbp + (size_t)r * DIN + c * 8);
        }
    }
}

// load all 8 fragments (4 A + 4 B) for one ks step into the given buffers
static __device__ __forceinline__ void load_frags(uint32_t abase, uint32_t bbase,
                                                  uint32_t arow, uint32_t brow,
                                                  int ks, int lane,
                                                  uint32_t A[4][4], uint32_t Bf[4][4]) {
    const uint32_t akh = (uint32_t)(ks * 16 + ((lane >> 4) << 3));
    const uint32_t bkh = (uint32_t)(ks * 16 + ((lane >> 3) & 1) * 8);
    #pragma unroll
    for (int q = 0; q < 4; ++q)
        ldsm4(A[q], abase + swz((arow + (uint32_t)(q * 16)) * 128 + akh * 2));
    #pragma unroll
    for (int q = 0; q < 4; ++q)
        ldsm4(Bf[q], bbase + swz((brow + (uint32_t)(q * 16)) * 128 + bkh * 2));
}

__global__ void __launch_bounds__(128, 2)
moe_gemm_kernel(float* __restrict__ out, const float* __restrict__ pb) {
    extern __shared__ char smem[];
    const uint32_t sb = smem_u32(smem);
    const int tid    = threadIdx.x;
    const int lane   = tid & 31;
    const int wid    = tid >> 5;                // 4 warps: 2(m) x 2(n)
    const int warp_n = wid & 1;                 // 2 n-warps x 64 cols
    const int warp_m = wid >> 1;                // 2 m-warps x 64 rows
    const int m_tile = blockIdx.x & 31;         // bid = n_tile*32 + m_tile (B panel L2 reuse)
    const int n_tile = blockIdx.x >> 5;
    const int m_base = m_tile * MT;
    const int n_base = n_tile * NT;
    const int o_base = n_tile * 4;              // NT=128 cols = 4 outputs x 32 leaves

    // prologue: stages 0..1
    #pragma unroll
    for (int p = 0; p < STG - 1; ++p) {
        load_tile(sb, tid, m_base, n_base, p, p);
        asm volatile("cp.async.commit_group;" ::: "memory");
    }

    float acc[4][8][4];                         // 4 m-frags x 8 n8-frags x 4 regs
    #pragma unroll
    for (int a = 0; a < 4; ++a)
        #pragma unroll
        for (int b = 0; b < 8; ++b)
            #pragma unroll
            for (int c = 0; c < 4; ++c) acc[a][b][c] = 0.f;

    const uint32_t arow = (uint32_t)(warp_m * 64 + (lane & 15));
    const uint32_t brow = (uint32_t)(warp_n * 64 + (lane & 7) + ((lane & 16) ? 8 : 0));

    uint32_t Af[2][4][4], Bf[2][4][4];          // double-buffered fragments

    #pragma unroll 1
    for (int t = 0; t < KI; ++t) {
        const int buf = t % STG;
        asm volatile("cp.async.wait_group %0;" :: "n"(STG - 2) : "memory");
        __syncthreads();
        const uint32_t abase = sb + buf * STAGE_BYTES;
        const uint32_t bbase = abase + SA_BYTES;

        // head: fragments for ks=0
        load_frags(abase, bbase, arow, brow, 0, lane, Af[0], Bf[0]);

        // issue next-tile cp.async early so LSU work overlaps the MMA block
        if (t + STG - 1 < KI)
            load_tile(sb, tid, m_base, n_base, t + STG - 1, (t + STG - 1) % STG);
        asm volatile("cp.async.commit_group;" ::: "memory");   // empty group keeps counts

        #pragma unroll
        for (int ks = 0; ks < 4; ++ks) {
            const int cur = ks & 1;
            if (ks < 3)                          // prefetch ks+1 fragments
                load_frags(abase, bbase, arow, brow, ks + 1, lane,
                           Af[cur ^ 1], Bf[cur ^ 1]);
            #pragma unroll
            for (int mf = 0; mf < 4; ++mf)
                #pragma unroll
                for (int nf = 0; nf < 8; ++nf)
                    mma16816(acc[mf][nf], Af[cur][mf],
                             Bf[cur][nf >> 1][(nf & 1) * 2],
                             Bf[cur][nf >> 1][(nf & 1) * 2 + 1]);
        }
    }

    // drain cp.async, then reuse stage smem for epilogue tables
    asm volatile("cp.async.wait_group 0;" ::: "memory");
    __syncthreads();
    float* gs  = reinterpret_cast<float*>(smem);               // [128][33] = 16896 B
    float* pbs = reinterpret_cast<float*>(smem + 16896);       // [4][33]
    #pragma unroll
    for (int i = tid; i < MT * LEAF; i += 128) {
        int r = i >> 5, l = i & 31;
        gs[r * 33 + l] = d_gate[(size_t)(m_base + r) * LEAF + l];
    }
    pbs[(tid >> 5) * 33 + (tid & 31)] = pb[(o_base + (tid >> 5)) * LEAF + (tid & 31)];
    __syncthreads();

    // epilogue: warp covers cols [warp_n*64, +64) = 2 outputs x 32 leaves
    #pragma unroll
    for (int mf = 0; mf < 4; ++mf) {
        #pragma unroll
        for (int rh = 0; rh < 2; ++rh) {
            const int mrow = warp_m * 64 + mf * 16 + (lane >> 2) + rh * 8;
            #pragma unroll
            for (int og = 0; og < 2; ++og) {
                const int o_loc = warp_n * 2 + og;
                float a = 0.f;
                #pragma unroll
                for (int nf4 = 0; nf4 < 4; ++nf4) {
                    const int nf = og * 4 + nf4;
                    const int l  = nf4 * 8 + (lane & 3) * 2;
                    a = fmaf(acc[mf][nf][rh * 2 + 0] + pbs[o_loc * 33 + l],
                             gs[mrow * 33 + l], a);
                    a = fmaf(acc[mf][nf][rh * 2 + 1] + pbs[o_loc * 33 + l + 1],
                             gs[mrow * 33 + l + 1], a);
                }
                a += __shfl_xor_sync(0xffffffff, a, 1);
                a += __shfl_xor_sync(0xffffffff, a, 2);
                if ((lane & 3) == 0)
                    out[(size_t)(m_base + mrow) * DOUT + o_base + o_loc] = a;
            }
        }
    }
}

// ---------------- launch ----------------
extern "C" void kernel_launch(void* const* d_in, const int* in_sizes, int n_in,
                              void* d_out, int out_size) {
    const float* x  = (const float*)d_in[0];   // [4096,1024]
    const float* gw = (const float*)d_in[1];   // [1024,32]
    const float* gb = (const float*)d_in[2];   // [32]
    const float* pw = (const float*)d_in[3];   // [1024,1024,32]
    const float* pb = (const float*)d_in[4];   // [1024,32]
    float* out = (float*)d_out;                // [4096,1024]

    cudaFuncSetAttribute(moe_gemm_kernel,
                         cudaFuncAttributeMaxDynamicSharedMemorySize, SMEM_TOTAL);

    gating_kernel<<<BROWS / 8, 256>>>(x, gw, gb);       // 512 blocks, 4096 warps
    pack_pw_kernel<<<dim3(DOUT, DIN / 64), 256>>>(pw);
    moe_gemm_kernel<<<32 * (NTOT / NT), 128, SMEM_TOTAL>>>(out, pb);
}

// round 15
// speedup vs baseline: 1.0202x; 1.0202x over previous
#include <cuda_runtime.h>
#include <cuda_fp16.h>
#include <cstdint>
#include <cstddef>

#define BROWS 4096
#define DIN   1024
#define DOUT  1024
#define LEAF  32
#define NTOT  (DOUT * LEAF)   // 32768

// ---------------- scratch (device globals: allocation-free) ----------------
__device__ __align__(128) __half d_xb[(size_t)BROWS * DIN];     // 8 MB   x fp16
__device__ __align__(128) __half d_pwb[(size_t)NTOT * DIN];     // 64 MB  pw packed [n=o*32+l][k=i]
__device__ __align__(128) float  d_gate[(size_t)BROWS * LEAF];  // 512 KB gates

// ---------------- helpers ----------------
static __device__ __forceinline__ uint32_t smem_u32(const void* p) {
    uint32_t a;
    asm("{ .reg .u64 t; cvta.to.shared.u64 t, %1; cvt.u32.u64 %0, t; }" : "=r"(a) : "l"(p));
    return a;
}
static __device__ __forceinline__ uint32_t swz(uint32_t o) {     // Swizzle<3,4,3>, 128B rows
    return o ^ ((o >> 3) & 0x70);
}
static __device__ __forceinline__ void cp_async16(uint32_t s, const void* g) {
    asm volatile("cp.async.cg.shared.global [%0], [%1], 16;" :: "r"(s), "l"(g));
}
static __device__ __forceinline__ void ldsm4(uint32_t* r, uint32_t addr) {
    asm volatile("ldmatrix.sync.aligned.m8n8.x4.shared.b16 {%0,%1,%2,%3}, [%4];"
                 : "=r"(r[0]), "=r"(r[1]), "=r"(r[2]), "=r"(r[3]) : "r"(addr));
}
static __device__ __forceinline__ void mma16816(float* d, const uint32_t* a,
                                                uint32_t b0, uint32_t b1) {
    asm volatile("mma.sync.aligned.m16n8k16.row.col.f32.f16.f16.f32 "
                 "{%0,%1,%2,%3}, {%4,%5,%6,%7}, {%8,%9}, {%0,%1,%2,%3};"
                 : "+f"(d[0]), "+f"(d[1]), "+f"(d[2]), "+f"(d[3])
                 : "r"(a[0]), "r"(a[1]), "r"(a[2]), "r"(a[3]), "r"(b0), "r"(b1));
}

// ---------------- kernel 1: FUSED prep ----------------
// blocks [0, 512):       gating softmax + x fp32->fp16 (8 rows per block)
// blocks [512, 512+16384): pack pw [O,I,L] fp32 -> pwb [(o*32+l), i] fp16
// Latency-bound gating blocks interleave with bandwidth-bound pack blocks.
#define GATE_BLKS (BROWS / 8)           // 512
#define PACK_BLKS (DOUT * (DIN / 64))   // 16384

__global__ void __launch_bounds__(256)
prep_kernel(const float* __restrict__ x, const float* __restrict__ gw,
            const float* __restrict__ gb, const float* __restrict__ pw) {
    __shared__ __align__(16) char sbuf[64 * 33 * 4];     // 8448 B, unioned
    const int tid  = threadIdx.x;

    if (blockIdx.x < GATE_BLKS) {
        // ---- gating: 8 warps x 8 rows, warp w does DIN-slice [w*128,(w+1)*128) ----
        float (*part)[8][32] = reinterpret_cast<float(*)[8][32]>(sbuf);  // [warp][row][lane]
        const int lane = tid & 31;
        const int w    = tid >> 5;
        const int r0   = blockIdx.x * 8;
        const float4* x4 = reinterpret_cast<const float4*>(x);

        float acc[8];
        #pragma unroll
        for (int r = 0; r < 8; ++r) acc[r] = 0.f;

        #pragma unroll 2
        for (int jj = 0; jj < 32; ++jj) {
            const int j = w * 32 + jj;
            const float* gp = gw + (j * 4) * LEAF + lane;
            const float g0 = gp[0 * LEAF];
            const float g1 = gp[1 * LEAF];
            const float g2 = gp[2 * LEAF];
            const float g3 = gp[3 * LEAF];
            #pragma unroll
            for (int r = 0; r < 8; ++r) {
                const float4 xv = x4[(size_t)(r0 + r) * (DIN / 4) + j];  // broadcast
                acc[r] = fmaf(xv.x, g0, acc[r]);
                acc[r] = fmaf(xv.y, g1, acc[r]);
                acc[r] = fmaf(xv.z, g2, acc[r]);
                acc[r] = fmaf(xv.w, g3, acc[r]);
            }
        }
        #pragma unroll
        for (int r = 0; r < 8; ++r) part[w][r][lane] = acc[r];

        // fp16 conversion of the block's 8 rows (overlaps the smem rendezvous)
        #pragma unroll
        for (int u = 0; u < 8; ++u) {
            const int idx = u * 256 + tid;
            const int r   = idx >> 8;
            const int c   = idx & 255;
            const float4 xv = x4[(size_t)(r0 + r) * (DIN / 4) + c];
            __half2* hp = reinterpret_cast<__half2*>(d_xb + (size_t)(r0 + r) * DIN) + c * 2;
            hp[0] = __floats2half2_rn(xv.x, xv.y);
            hp[1] = __floats2half2_rn(xv.z, xv.w);
        }
        __syncthreads();

        // warp w finalizes row w
        float a = gb[lane];
        #pragma unroll
        for (int k = 0; k < 8; ++k) a += part[k][w][lane];
        float m = a;
        #pragma unroll
        for (int o = 16; o; o >>= 1) m = fmaxf(m, __shfl_xor_sync(0xffffffff, m, o));
        const float e = expf(a - m);
        float s = e;
        #pragma unroll
        for (int o = 16; o; o >>= 1) s += __shfl_xor_sync(0xffffffff, s, o);
        d_gate[(size_t)(r0 + w) * LEAF + lane] = e / s;
    } else {
        // ---- pack: transpose one (o, i0) tile of pw into pwb, float4 reads ----
        float (*tile)[33] = reinterpret_cast<float(*)[33]>(sbuf);       // [64][33]
        const int v   = blockIdx.x - GATE_BLKS;
        const int o   = v >> 4;                           // 0..1023
        const int i0  = (v & 15) << 6;                    // 0..960
        const float4* src4 =
            reinterpret_cast<const float4*>(pw + ((size_t)o * DIN + i0) * LEAF);
        #pragma unroll
        for (int u = 0; u < 2; ++u) {                     // 512 float4 = 2048 floats
            const int j = u * 256 + tid;
            const float4 val = src4[j];
            const int r = j >> 3, c = (j & 7) * 4;
            tile[r][c + 0] = val.x;
            tile[r][c + 1] = val.y;
            tile[r][c + 2] = val.z;
            tile[r][c + 3] = val.w;
        }
        __syncthreads();
        __half2* dst2 = reinterpret_cast<__half2*>(d_pwb + ((size_t)o * LEAF) * DIN + i0);
        #pragma unroll
        for (int u = 0; u < 4; ++u) {                     // 1024 coalesced half2 writes
            const int idx = u * 256 + tid;
            const int l = idx >> 5, p = idx & 31;
            dst2[(size_t)l * (DIN / 2) + p] =
                __floats2half2_rn(tile[2 * p][l], tile[2 * p + 1][l]);
        }
    }
}

// ---------------- kernel 2: mma.sync GEMM, 2 CTA/SM, warp tile 64x64 (R12) ----------------
#define MT  128
#define NT  128
#define KT  64                       // halves per k-tile (128 B rows)
#define KI  (DIN / KT)               // 16
#define STG 3
#define SA_BYTES    (MT * KT * 2)    // 16384
#define SB_BYTES    (NT * KT * 2)    // 16384
#define STAGE_BYTES (SA_BYTES + SB_BYTES)          // 32768
#define SMEM_TOTAL  (STG * STAGE_BYTES)            // 98304 -> 2 CTAs/SM

static __device__ __forceinline__ void load_tile(uint32_t sb, int tid,
                                                 int m_base, int n_base, int ki, int buf) {
    const uint32_t abase = sb + buf * STAGE_BYTES;
    const uint32_t bbase = abase + SA_BYTES;
    const __half* ga  = d_xb  + (size_t)m_base * DIN + ki * KT;
    const __half* gbp = d_pwb + (size_t)n_base * DIN + ki * KT;
    #pragma unroll
    for (int u = 0; u < 16; ++u) {                        // 2048 x 16B chunks / 128 thr
        const int idx = u * 128 + tid;
        if (idx < 1024) {                                 // A: 128 rows x 8 chunks
            const int r = idx >> 3, c = idx & 7;
            cp_async16(abase + swz((uint32_t)(r * 128 + c * 16)),
                       ga + (size_t)r * DIN + c * 8);
        } else {                                          // B: 128 rows x 8 chunks
            const int j = idx - 1024;
            const int r = j >> 3, c = j & 7;
            cp_async16(bbase + swz((uint32_t)(r * 128 + c * 16)),
                       gbp + (size_t)r * DIN + c * 8);
        }
    }
}

__global__ void __launch_bounds__(128, 2)
moe_gemm_kernel(float* __restrict__ out, const float* __restrict__ pb) {
    extern __shared__ char smem[];
    const uint32_t sb = smem_u32(smem);
    const int tid    = threadIdx.x;
    const int lane   = tid & 31;
    const int wid    = tid >> 5;                // 4 warps: 2(m) x 2(n)
    const int warp_n = wid & 1;                 // 2 n-warps x 64 cols
    const int warp_m = wid >> 1;                // 2 m-warps x 64 rows
    const int m_tile = blockIdx.x & 31;         // bid = n_tile*32 + m_tile (B panel L2 reuse)
    const int n_tile = blockIdx.x >> 5;
    const int m_base = m_tile * MT;
    const int n_base = n_tile * NT;
    const int o_base = n_tile * 4;              // NT=128 cols = 4 outputs x 32 leaves

    // prologue: stages 0..1
    #pragma unroll
    for (int p = 0; p < STG - 1; ++p) {
        load_tile(sb, tid, m_base, n_base, p, p);
        asm volatile("cp.async.commit_group;" ::: "memory");
    }

    float acc[4][8][4];                         // 4 m-frags x 8 n8-frags x 4 regs
    #pragma unroll
    for (int a = 0; a < 4; ++a)
        #pragma unroll
        for (int b = 0; b < 8; ++b)
            #pragma unroll
            for (int c = 0; c < 4; ++c) acc[a][b][c] = 0.f;

    const uint32_t arow = (uint32_t)(warp_m * 64 + (lane & 15));
    const uint32_t brow = (uint32_t)(warp_n * 64 + (lane & 7) + ((lane & 16) ? 8 : 0));

    #pragma unroll 1
    for (int t = 0; t < KI; ++t) {
        const int buf = t % STG;
        asm volatile("cp.async.wait_group %0;" :: "n"(STG - 2) : "memory");
        __syncthreads();
        const uint32_t abase = sb + buf * STAGE_BYTES;
        const uint32_t bbase = abase + SA_BYTES;
        #pragma unroll
        for (int ks = 0; ks < 4; ++ks) {
            const uint32_t akh = (uint32_t)(ks * 16 + ((lane >> 4) << 3));
            const uint32_t bkh = (uint32_t)(ks * 16 + ((lane >> 3) & 1) * 8);
            uint32_t A[4][4];
            #pragma unroll
            for (int q = 0; q < 4; ++q)
                ldsm4(A[q], abase + swz((arow + (uint32_t)(q * 16)) * 128 + akh * 2));
            uint32_t Bf[4][4];
            #pragma unroll
            for (int q = 0; q < 4; ++q)
                ldsm4(Bf[q], bbase + swz((brow + (uint32_t)(q * 16)) * 128 + bkh * 2));
            #pragma unroll
            for (int mf = 0; mf < 4; ++mf)
                #pragma unroll
                for (int nf = 0; nf < 8; ++nf)
                    mma16816(acc[mf][nf], A[mf],
                             Bf[nf >> 1][(nf & 1) * 2], Bf[nf >> 1][(nf & 1) * 2 + 1]);
        }
        if (t + STG - 1 < KI)
            load_tile(sb, tid, m_base, n_base, t + STG - 1, (t + STG - 1) % STG);
        asm volatile("cp.async.commit_group;" ::: "memory");   // empty group keeps counts
    }

    // drain cp.async, then reuse stage smem for epilogue tables
    asm volatile("cp.async.wait_group 0;" ::: "memory");
    __syncthreads();
    float* gs  = reinterpret_cast<float*>(smem);               // [128][33] = 16896 B
    float* pbs = reinterpret_cast<float*>(smem + 16896);       // [4][33]
    #pragma unroll
    for (int i = tid; i < MT * LEAF; i += 128) {
        int r = i >> 5, l = i & 31;
        gs[r * 33 + l] = d_gate[(size_t)(m_base + r) * LEAF + l];
    }
    pbs[(tid >> 5) * 33 + (tid & 31)] = pb[(o_base + (tid >> 5)) * LEAF + (tid & 31)];
    __syncthreads();

    // epilogue: warp covers cols [warp_n*64, +64) = 2 outputs x 32 leaves
    #pragma unroll
    for (int mf = 0; mf < 4; ++mf) {
        #pragma unroll
        for (int rh = 0; rh < 2; ++rh) {
            const int mrow = warp_m * 64 + mf * 16 + (lane >> 2) + rh * 8;
            #pragma unroll
            for (int og = 0; og < 2; ++og) {
                const int o_loc = warp_n * 2 + og;
                float a = 0.f;
                #pragma unroll
                for (int nf4 = 0; nf4 < 4; ++nf4) {
                    const int nf = og * 4 + nf4;
                    const int l  = nf4 * 8 + (lane & 3) * 2;
                    a = fmaf(acc[mf][nf][rh * 2 + 0] + pbs[o_loc * 33 + l],
                             gs[mrow * 33 + l], a);
                    a = fmaf(acc[mf][nf][rh * 2 + 1] + pbs[o_loc * 33 + l + 1],
                             gs[mrow * 33 + l + 1], a);
                }
                a += __shfl_xor_sync(0xffffffff, a, 1);
                a += __shfl_xor_sync(0xffffffff, a, 2);
                if ((lane & 3) == 0)
                    out[(size_t)(m_base + mrow) * DOUT + o_base + o_loc] = a;
            }
        }
    }
}

// ---------------- launch ----------------
extern "C" void kernel_launch(void* const* d_in, const int* in_sizes, int n_in,
                              void* d_out, int out_size) {
    const float* x  = (const float*)d_in[0];   // [4096,1024]
    const float* gw = (const float*)d_in[1];   // [1024,32]
    const float* gb = (const float*)d_in[2];   // [32]
    const float* pw = (const float*)d_in[3];   // [1024,1024,32]
    const float* pb = (const float*)d_in[4];   // [1024,32]
    float* out = (float*)d_out;                // [4096,1024]

    cudaFuncSetAttribute(moe_gemm_kernel,
                         cudaFuncAttributeMaxDynamicSharedMemorySize, SMEM_TOTAL);

    prep_kernel<<<GATE_BLKS + PACK_BLKS, 256>>>(x, gw, gb, pw);
    moe_gemm_kernel<<<32 * (NTOT / NT), 128, SMEM_TOTAL>>>(out, pb);
}